// round 3
// baseline (speedup 1.0000x reference)
#include <cuda_runtime.h>

#define Nn 50000
#define Ee 800000
#define Hh 64
#define Ll 4
#define Gg 500
#define Cc 10
#define BN_EPS 1e-5f

// ---------------- device scratch (static, no allocations; 16B-aligned for v4 ops) ----------------
__device__ __align__(16) float g_agg[(size_t)Nn * Hh];    // 12.8 MB, neighbor-sum accumulator
__device__ __align__(16) float g_h[(size_t)Ll * Nn * Hh]; // 51.2 MB, per-layer outputs (JK cat source)
__device__ __align__(16) float g_W1[Ll * Hh * Hh];        // BN1-folded weights
__device__ __align__(16) float g_W2[Ll * Hh * Hh];        // BN2-folded weights
__device__ __align__(16) float g_c1[Ll * Hh];             // folded bias 1
__device__ __align__(16) float g_c2[Ll * Hh];             // folded bias 2
__device__ __align__(16) float g_pool[Gg * Ll * Hh];      // pooled [G, L*H]

// ---------------- zero scratch ----------------
__global__ void zero_k() {
    int t = blockIdx.x * blockDim.x + threadIdx.x;
    const int tot_agg = Nn * Hh / 4;
    const int tot_pool = Gg * Ll * Hh / 4;
    float4 z = make_float4(0.f, 0.f, 0.f, 0.f);
    if (t < tot_agg)  reinterpret_cast<float4*>(g_agg)[t] = z;
    if (t < tot_pool) reinterpret_cast<float4*>(g_pool)[t] = z;
}

// ---------------- fold BN into weights/bias ----------------
// y = bn(z@W + b) = z @ (W * s) + (b*s + beta - m*s), s = g * rsqrt(v + eps)
__global__ void fold_k(const float* __restrict__ W1, const float* __restrict__ b1,
                       const float* __restrict__ g1, const float* __restrict__ be1,
                       const float* __restrict__ m1, const float* __restrict__ v1,
                       const float* __restrict__ W2, const float* __restrict__ b2,
                       const float* __restrict__ g2, const float* __restrict__ be2,
                       const float* __restrict__ m2, const float* __restrict__ v2) {
    int idx = blockIdx.x * blockDim.x + threadIdx.x;
    if (idx >= Ll * Hh * Hh) return;
    int j = idx & (Hh - 1);
    int lk = idx >> 6;
    int l = lk >> 6;
    int k = lk & 63;
    int lj = l * Hh + j;
    float s1 = g1[lj] * rsqrtf(v1[lj] + BN_EPS);
    float s2 = g2[lj] * rsqrtf(v2[lj] + BN_EPS);
    g_W1[idx] = W1[idx] * s1;
    g_W2[idx] = W2[idx] * s2;
    if (k == 0) {
        g_c1[lj] = b1[lj] * s1 + be1[lj] - m1[lj] * s1;
        g_c2[lj] = b2[lj] * s2 + be2[lj] - m2[lj] * s2;
    }
}

// ---------------- edge scatter: agg[dst] += h[src], vector red (int32 indices!) ----------------
__global__ void scatter_k(const float* __restrict__ h, const int* __restrict__ ei) {
    int t = blockIdx.x * blockDim.x + threadIdx.x;
    if (t >= Ee * 16) return;           // 16 float4-chunks per edge (H=64)
    int e = t >> 4;
    int c = (t & 15) << 2;
    int s = __ldg(ei + e);
    int d = __ldg(ei + Ee + e);
    float4 v = *reinterpret_cast<const float4*>(h + (size_t)s * Hh + c);
    float* p = g_agg + (size_t)d * Hh + c;
    asm volatile("red.global.add.v4.f32 [%0], {%1,%2,%3,%4};"
                 :: "l"(p), "f"(v.x), "f"(v.y), "f"(v.z), "f"(v.w) : "memory");
}

// ---------------- fused GIN MLP ----------------
// Block = 256 threads handles 64 rows. 4x4 register tile per thread.
// Also zeroes its agg rows after consuming them (ready for next layer's scatter).
__global__ void __launch_bounds__(256) mlp_k(const float* __restrict__ hin,
                                             float* __restrict__ hout, int layer) {
    __shared__ __align__(16) float sZ[64][68];   // stride 68 floats: 272B rows, 16B-aligned
    __shared__ __align__(16) float sW[64 * 64];

    int tid = threadIdx.x;
    int row0 = blockIdx.x * 64;

    // load z = hin + agg (and zero agg)
    for (int i = tid; i < 1024; i += 256) {
        int r = i >> 4;
        int c = (i & 15) << 2;
        int gr = row0 + r;
        float4 z = make_float4(0.f, 0.f, 0.f, 0.f);
        if (gr < Nn) {
            size_t off = (size_t)gr * Hh + c;
            float4 a = *reinterpret_cast<const float4*>(g_agg + off);
            float4 hv = *reinterpret_cast<const float4*>(hin + off);
            z.x = a.x + hv.x; z.y = a.y + hv.y; z.z = a.z + hv.z; z.w = a.w + hv.w;
            *reinterpret_cast<float4*>(g_agg + off) = make_float4(0.f, 0.f, 0.f, 0.f);
        }
        *reinterpret_cast<float4*>(&sZ[r][c]) = z;
    }
    // load W1'
    {
        const float* Wg = g_W1 + layer * Hh * Hh;
        for (int i = tid * 4; i < 4096; i += 1024)
            *reinterpret_cast<float4*>(sW + i) = *reinterpret_cast<const float4*>(Wg + i);
    }
    __syncthreads();

    int tx = tid & 15;          // output column group (4 cols)
    int ty = tid >> 4;          // output row group   (4 rows)

    float acc[4][4];
    #pragma unroll
    for (int i = 0; i < 4; i++)
        #pragma unroll
        for (int j = 0; j < 4; j++) acc[i][j] = 0.f;

    // GEMM1
    #pragma unroll 16
    for (int k = 0; k < 64; k++) {
        float4 w = *reinterpret_cast<const float4*>(sW + k * 64 + tx * 4);
        #pragma unroll
        for (int i = 0; i < 4; i++) {
            float zv = sZ[ty * 4 + i][k];
            acc[i][0] = fmaf(zv, w.x, acc[i][0]);
            acc[i][1] = fmaf(zv, w.y, acc[i][1]);
            acc[i][2] = fmaf(zv, w.z, acc[i][2]);
            acc[i][3] = fmaf(zv, w.w, acc[i][3]);
        }
    }
    float4 c1v = *reinterpret_cast<const float4*>(g_c1 + layer * Hh + tx * 4);
    __syncthreads();   // everyone done reading sZ/sW

    // y1 = relu(acc + c1) -> overwrite sZ; reload sW with W2'
    #pragma unroll
    for (int i = 0; i < 4; i++) {
        float4 y;
        y.x = fmaxf(acc[i][0] + c1v.x, 0.f);
        y.y = fmaxf(acc[i][1] + c1v.y, 0.f);
        y.z = fmaxf(acc[i][2] + c1v.z, 0.f);
        y.w = fmaxf(acc[i][3] + c1v.w, 0.f);
        *reinterpret_cast<float4*>(&sZ[ty * 4 + i][tx * 4]) = y;
    }
    {
        const float* Wg = g_W2 + layer * Hh * Hh;
        for (int i = tid * 4; i < 4096; i += 1024)
            *reinterpret_cast<float4*>(sW + i) = *reinterpret_cast<const float4*>(Wg + i);
    }
    __syncthreads();

    #pragma unroll
    for (int i = 0; i < 4; i++)
        #pragma unroll
        for (int j = 0; j < 4; j++) acc[i][j] = 0.f;

    // GEMM2
    #pragma unroll 16
    for (int k = 0; k < 64; k++) {
        float4 w = *reinterpret_cast<const float4*>(sW + k * 64 + tx * 4);
        #pragma unroll
        for (int i = 0; i < 4; i++) {
            float zv = sZ[ty * 4 + i][k];
            acc[i][0] = fmaf(zv, w.x, acc[i][0]);
            acc[i][1] = fmaf(zv, w.y, acc[i][1]);
            acc[i][2] = fmaf(zv, w.z, acc[i][2]);
            acc[i][3] = fmaf(zv, w.w, acc[i][3]);
        }
    }
    float4 c2v = *reinterpret_cast<const float4*>(g_c2 + layer * Hh + tx * 4);
    #pragma unroll
    for (int i = 0; i < 4; i++) {
        int gr = row0 + ty * 4 + i;
        if (gr < Nn) {
            float4 y;
            y.x = fmaxf(acc[i][0] + c2v.x, 0.f);
            y.y = fmaxf(acc[i][1] + c2v.y, 0.f);
            y.z = fmaxf(acc[i][2] + c2v.z, 0.f);
            y.w = fmaxf(acc[i][3] + c2v.w, 0.f);
            *reinterpret_cast<float4*>(hout + (size_t)gr * Hh + tx * 4) = y;
        }
    }
}

// ---------------- pooled[batch[n]][l*64+c] += h_l[n][c]  (int32 batch!) ----------------
__global__ void pool_k(const int* __restrict__ batch) {
    int t = blockIdx.x * blockDim.x + threadIdx.x;
    if (t >= Nn * 64) return;           // 64 = L * 16 chunks per node
    int n = t >> 6;
    int chunk = t & 63;
    int l = chunk >> 4;
    int c = (chunk & 15) << 2;
    int g = __ldg(batch + n);
    float4 v = *reinterpret_cast<const float4*>(g_h + ((size_t)l * Nn + n) * Hh + c);
    float* p = g_pool + (size_t)g * (Ll * Hh) + l * Hh + c;
    asm volatile("red.global.add.v4.f32 [%0], {%1,%2,%3,%4};"
                 :: "l"(p), "f"(v.x), "f"(v.y), "f"(v.z), "f"(v.w) : "memory");
}

// ---------------- head: relu(pooled @ lin1 + b1) @ lin2 + b2 ----------------
__global__ void final_k(const float* __restrict__ W1, const float* __restrict__ b1,
                        const float* __restrict__ W2, const float* __restrict__ b2,
                        float* __restrict__ out) {
    int g = blockIdx.x;
    int j = threadIdx.x;   // 64 threads
    __shared__ float sp[Ll * Hh];
    __shared__ float sh[Hh];
    for (int i = j; i < Ll * Hh; i += 64) sp[i] = g_pool[(size_t)g * (Ll * Hh) + i];
    __syncthreads();
    float a = b1[j];
    #pragma unroll 8
    for (int k = 0; k < Ll * Hh; k++) a = fmaf(sp[k], W1[k * Hh + j], a);
    sh[j] = fmaxf(a, 0.f);
    __syncthreads();
    if (j < Cc) {
        float o = b2[j];
        #pragma unroll
        for (int k = 0; k < Hh; k++) o = fmaf(sh[k], W2[k * Cc + j], o);
        out[g * Cc + j] = o;
    }
}

// ---------------- launch ----------------
extern "C" void kernel_launch(void* const* d_in, const int* in_sizes, int n_in,
                              void* d_out, int out_size) {
    const float* x     = (const float*)d_in[0];
    const int*   ei    = (const int*)d_in[1];      // int32 on device (harness downcasts int64)
    const int*   batch = (const int*)d_in[2];      // int32 on device
    const float* cW1 = (const float*)d_in[3];
    const float* cb1 = (const float*)d_in[4];
    const float* g1  = (const float*)d_in[5];
    const float* be1 = (const float*)d_in[6];
    const float* m1  = (const float*)d_in[7];
    const float* v1  = (const float*)d_in[8];
    const float* cW2 = (const float*)d_in[9];
    const float* cb2 = (const float*)d_in[10];
    const float* g2  = (const float*)d_in[11];
    const float* be2 = (const float*)d_in[12];
    const float* m2  = (const float*)d_in[13];
    const float* v2  = (const float*)d_in[14];
    const float* l1W = (const float*)d_in[15];
    const float* l1b = (const float*)d_in[16];
    const float* l2W = (const float*)d_in[17];
    const float* l2b = (const float*)d_in[18];
    float* out = (float*)d_out;

    // zero agg + pooled
    zero_k<<<(Nn * Hh / 4 + 255) / 256, 256>>>();
    // fold BN into weights
    fold_k<<<(Ll * Hh * Hh + 255) / 256, 256>>>(cW1, cb1, g1, be1, m1, v1,
                                                cW2, cb2, g2, be2, m2, v2);

    float* hbase;
    cudaGetSymbolAddress((void**)&hbase, g_h);

    const float* hin = x;
    for (int l = 0; l < Ll; l++) {
        scatter_k<<<(Ee * 16 + 255) / 256, 256>>>(hin, ei);
        float* hout = hbase + (size_t)l * Nn * Hh;
        mlp_k<<<(Nn + 63) / 64, 256>>>(hin, hout, l);   // also re-zeroes agg
        hin = hout;
    }
    pool_k<<<(Nn * 64 + 255) / 256, 256>>>(batch);
    final_k<<<Gg, 64>>>(l1W, l1b, l2W, l2b, out);
}

// round 4
// speedup vs baseline: 1.2054x; 1.2054x over previous
#include <cuda_runtime.h>

#define Nn 50000
#define Ee 800000
#define Hh 64
#define Ll 4
#define Gg 500
#define Cc 10
#define BN_EPS 1e-5f

// ---------------- device scratch (static, 16B-aligned) ----------------
__device__ __align__(16) float g_agg[(size_t)Nn * Hh];    // z accumulator: prefilled with self term, scatter adds neighbors
__device__ __align__(16) float g_h[(size_t)Ll * Nn * Hh]; // per-layer outputs (JK cat source)
__device__ __align__(16) float g_W1[Ll * Hh * Hh];
__device__ __align__(16) float g_W2[Ll * Hh * Hh];
__device__ __align__(16) float g_c1[Ll * Hh];
__device__ __align__(16) float g_c2[Ll * Hh];
__device__ __align__(16) float g_pool[Gg * Ll * Hh];

// ---------------- init: agg = x (self term, layer 0), pool = 0 ----------------
__global__ void init_k(const float* __restrict__ x) {
    int t = blockIdx.x * blockDim.x + threadIdx.x;
    const int tot_agg = Nn * Hh / 4;
    const int tot_pool = Gg * Ll * Hh / 4;
    if (t < tot_agg)
        reinterpret_cast<float4*>(g_agg)[t] = reinterpret_cast<const float4*>(x)[t];
    if (t < tot_pool)
        reinterpret_cast<float4*>(g_pool)[t] = make_float4(0.f, 0.f, 0.f, 0.f);
}

// ---------------- fold BN into weights/bias ----------------
__global__ void fold_k(const float* __restrict__ W1, const float* __restrict__ b1,
                       const float* __restrict__ g1, const float* __restrict__ be1,
                       const float* __restrict__ m1, const float* __restrict__ v1,
                       const float* __restrict__ W2, const float* __restrict__ b2,
                       const float* __restrict__ g2, const float* __restrict__ be2,
                       const float* __restrict__ m2, const float* __restrict__ v2) {
    int idx = blockIdx.x * blockDim.x + threadIdx.x;
    if (idx >= Ll * Hh * Hh) return;
    int j = idx & (Hh - 1);
    int lk = idx >> 6;
    int l = lk >> 6;
    int k = lk & 63;
    int lj = l * Hh + j;
    float s1 = g1[lj] * rsqrtf(v1[lj] + BN_EPS);
    float s2 = g2[lj] * rsqrtf(v2[lj] + BN_EPS);
    g_W1[idx] = W1[idx] * s1;
    g_W2[idx] = W2[idx] * s2;
    if (k == 0) {
        g_c1[lj] = b1[lj] * s1 + be1[lj] - m1[lj] * s1;
        g_c2[lj] = b2[lj] * s2 + be2[lj] - m2[lj] * s2;
    }
}

// ---------------- edge scatter: agg[dst] += h[src] (agg prefilled with self term) ----------------
__global__ void scatter_k(const float* __restrict__ h, const int* __restrict__ ei) {
    int t = blockIdx.x * blockDim.x + threadIdx.x;
    if (t >= Ee * 16) return;
    int e = t >> 4;
    int c = (t & 15) << 2;
    int s = __ldg(ei + e);
    int d = __ldg(ei + Ee + e);
    float4 v = *reinterpret_cast<const float4*>(h + (size_t)s * Hh + c);
    float* p = g_agg + (size_t)d * Hh + c;
    asm volatile("red.global.add.v4.f32 [%0], {%1,%2,%3,%4};"
                 :: "l"(p), "f"(v.x), "f"(v.y), "f"(v.z), "f"(v.w) : "memory");
}

// ---------------- fused GIN MLP ----------------
// Reads z directly from g_agg (already = h + sum_neighbors).
// Writes hout to g_h[layer]; if prefill, also writes hout into g_agg
// (self term for next layer's scatter). 256 thr / 64 rows, 4x4 reg tile,
// float4 smem reads on both operands, occupancy-capped regs.
__global__ void __launch_bounds__(256, 5) mlp_k(float* __restrict__ hout,
                                                int layer, int prefill) {
    __shared__ __align__(16) float sZ[64][68];   // 272B rows: 16B-aligned, conflict-free
    __shared__ __align__(16) float sW[64 * 64];

    int tid = threadIdx.x;
    int row0 = blockIdx.x * 64;

    // load z = agg
    for (int i = tid; i < 1024; i += 256) {
        int r = i >> 4;
        int c = (i & 15) << 2;
        int gr = row0 + r;
        float4 z = make_float4(0.f, 0.f, 0.f, 0.f);
        if (gr < Nn)
            z = *reinterpret_cast<const float4*>(g_agg + (size_t)gr * Hh + c);
        *reinterpret_cast<float4*>(&sZ[r][c]) = z;
    }
    {
        const float* Wg = g_W1 + layer * Hh * Hh;
        for (int i = tid * 4; i < 4096; i += 1024)
            *reinterpret_cast<float4*>(sW + i) = *reinterpret_cast<const float4*>(Wg + i);
    }
    __syncthreads();

    int tx = tid & 15;
    int ty = tid >> 4;

    float acc[4][4];
    #pragma unroll
    for (int i = 0; i < 4; i++)
        #pragma unroll
        for (int j = 0; j < 4; j++) acc[i][j] = 0.f;

    // GEMM1: k in chunks of 4, float4 loads for z and w
    #pragma unroll
    for (int k0 = 0; k0 < 64; k0 += 4) {
        float za[4][4];
        #pragma unroll
        for (int i = 0; i < 4; i++) {
            float4 z4 = *reinterpret_cast<const float4*>(&sZ[ty * 4 + i][k0]);
            za[i][0] = z4.x; za[i][1] = z4.y; za[i][2] = z4.z; za[i][3] = z4.w;
        }
        #pragma unroll
        for (int kk = 0; kk < 4; kk++) {
            float4 w = *reinterpret_cast<const float4*>(sW + (k0 + kk) * 64 + tx * 4);
            #pragma unroll
            for (int i = 0; i < 4; i++) {
                acc[i][0] = fmaf(za[i][kk], w.x, acc[i][0]);
                acc[i][1] = fmaf(za[i][kk], w.y, acc[i][1]);
                acc[i][2] = fmaf(za[i][kk], w.z, acc[i][2]);
                acc[i][3] = fmaf(za[i][kk], w.w, acc[i][3]);
            }
        }
    }
    float4 c1v = *reinterpret_cast<const float4*>(g_c1 + layer * Hh + tx * 4);
    __syncthreads();

    // y1 = relu(acc + c1) -> sZ; reload sW with W2'
    #pragma unroll
    for (int i = 0; i < 4; i++) {
        float4 y;
        y.x = fmaxf(acc[i][0] + c1v.x, 0.f);
        y.y = fmaxf(acc[i][1] + c1v.y, 0.f);
        y.z = fmaxf(acc[i][2] + c1v.z, 0.f);
        y.w = fmaxf(acc[i][3] + c1v.w, 0.f);
        *reinterpret_cast<float4*>(&sZ[ty * 4 + i][tx * 4]) = y;
    }
    {
        const float* Wg = g_W2 + layer * Hh * Hh;
        for (int i = tid * 4; i < 4096; i += 1024)
            *reinterpret_cast<float4*>(sW + i) = *reinterpret_cast<const float4*>(Wg + i);
    }
    __syncthreads();

    #pragma unroll
    for (int i = 0; i < 4; i++)
        #pragma unroll
        for (int j = 0; j < 4; j++) acc[i][j] = 0.f;

    // GEMM2
    #pragma unroll
    for (int k0 = 0; k0 < 64; k0 += 4) {
        float za[4][4];
        #pragma unroll
        for (int i = 0; i < 4; i++) {
            float4 z4 = *reinterpret_cast<const float4*>(&sZ[ty * 4 + i][k0]);
            za[i][0] = z4.x; za[i][1] = z4.y; za[i][2] = z4.z; za[i][3] = z4.w;
        }
        #pragma unroll
        for (int kk = 0; kk < 4; kk++) {
            float4 w = *reinterpret_cast<const float4*>(sW + (k0 + kk) * 64 + tx * 4);
            #pragma unroll
            for (int i = 0; i < 4; i++) {
                acc[i][0] = fmaf(za[i][kk], w.x, acc[i][0]);
                acc[i][1] = fmaf(za[i][kk], w.y, acc[i][1]);
                acc[i][2] = fmaf(za[i][kk], w.z, acc[i][2]);
                acc[i][3] = fmaf(za[i][kk], w.w, acc[i][3]);
            }
        }
    }
    float4 c2v = *reinterpret_cast<const float4*>(g_c2 + layer * Hh + tx * 4);
    #pragma unroll
    for (int i = 0; i < 4; i++) {
        int gr = row0 + ty * 4 + i;
        if (gr < Nn) {
            float4 y;
            y.x = fmaxf(acc[i][0] + c2v.x, 0.f);
            y.y = fmaxf(acc[i][1] + c2v.y, 0.f);
            y.z = fmaxf(acc[i][2] + c2v.z, 0.f);
            y.w = fmaxf(acc[i][3] + c2v.w, 0.f);
            size_t off = (size_t)gr * Hh + tx * 4;
            *reinterpret_cast<float4*>(hout + off) = y;
            if (prefill)
                *reinterpret_cast<float4*>(g_agg + off) = y;  // self term for next layer
        }
    }
}

// ---------------- pooled[batch[n]][l*64+c] += h_l[n][c] ----------------
__global__ void pool_k(const int* __restrict__ batch) {
    int t = blockIdx.x * blockDim.x + threadIdx.x;
    if (t >= Nn * 64) return;
    int n = t >> 6;
    int chunk = t & 63;
    int l = chunk >> 4;
    int c = (chunk & 15) << 2;
    int g = __ldg(batch + n);
    float4 v = *reinterpret_cast<const float4*>(g_h + ((size_t)l * Nn + n) * Hh + c);
    float* p = g_pool + (size_t)g * (Ll * Hh) + l * Hh + c;
    asm volatile("red.global.add.v4.f32 [%0], {%1,%2,%3,%4};"
                 :: "l"(p), "f"(v.x), "f"(v.y), "f"(v.z), "f"(v.w) : "memory");
}

// ---------------- head: relu(pooled @ lin1 + b1) @ lin2 + b2 ----------------
__global__ void final_k(const float* __restrict__ W1, const float* __restrict__ b1,
                        const float* __restrict__ W2, const float* __restrict__ b2,
                        float* __restrict__ out) {
    int g = blockIdx.x;
    int j = threadIdx.x;   // 64 threads
    __shared__ float sp[Ll * Hh];
    __shared__ float sh[Hh];
    for (int i = j; i < Ll * Hh; i += 64) sp[i] = g_pool[(size_t)g * (Ll * Hh) + i];
    __syncthreads();
    float a = b1[j];
    #pragma unroll 8
    for (int k = 0; k < Ll * Hh; k++) a = fmaf(sp[k], W1[k * Hh + j], a);
    sh[j] = fmaxf(a, 0.f);
    __syncthreads();
    if (j < Cc) {
        float o = b2[j];
        #pragma unroll
        for (int k = 0; k < Hh; k++) o = fmaf(sh[k], W2[k * Cc + j], o);
        out[g * Cc + j] = o;
    }
}

// ---------------- launch ----------------
extern "C" void kernel_launch(void* const* d_in, const int* in_sizes, int n_in,
                              void* d_out, int out_size) {
    const float* x     = (const float*)d_in[0];
    const int*   ei    = (const int*)d_in[1];
    const int*   batch = (const int*)d_in[2];
    const float* cW1 = (const float*)d_in[3];
    const float* cb1 = (const float*)d_in[4];
    const float* g1  = (const float*)d_in[5];
    const float* be1 = (const float*)d_in[6];
    const float* m1  = (const float*)d_in[7];
    const float* v1  = (const float*)d_in[8];
    const float* cW2 = (const float*)d_in[9];
    const float* cb2 = (const float*)d_in[10];
    const float* g2  = (const float*)d_in[11];
    const float* be2 = (const float*)d_in[12];
    const float* m2  = (const float*)d_in[13];
    const float* v2  = (const float*)d_in[14];
    const float* l1W = (const float*)d_in[15];
    const float* l1b = (const float*)d_in[16];
    const float* l2W = (const float*)d_in[17];
    const float* l2b = (const float*)d_in[18];
    float* out = (float*)d_out;

    init_k<<<(Nn * Hh / 4 + 255) / 256, 256>>>(x);   // agg = x, pool = 0
    fold_k<<<(Ll * Hh * Hh + 255) / 256, 256>>>(cW1, cb1, g1, be1, m1, v1,
                                                cW2, cb2, g2, be2, m2, v2);

    float* hbase;
    cudaGetSymbolAddress((void**)&hbase, g_h);

    const float* hin = x;
    for (int l = 0; l < Ll; l++) {
        scatter_k<<<(Ee * 16 + 255) / 256, 256>>>(hin, ei);
        float* hout = hbase + (size_t)l * Nn * Hh;
        mlp_k<<<(Nn + 63) / 64, 256>>>(hout, l, l < Ll - 1 ? 1 : 0);
        hin = hout;
    }
    pool_k<<<(Nn * 64 + 255) / 256, 256>>>(batch);
    final_k<<<Gg, 64>>>(l1W, l1b, l2W, l2b, out);
}